// round 2
// baseline (speedup 1.0000x reference)
#include <cuda_runtime.h>
#include <cstdint>
#include <math.h>

#define V_SZ 100000
#define H_SZ 300
#define B_SZ 64
#define L_SZ 64

#define VB 128          // vocab rows per logits block
#define KCH 20          // K chunk
#define NBLK_LOG 782    // 782*128 = 100096 >= V_SZ

typedef unsigned long long ull;

// ---------------- device scratch (no allocations allowed) ----------------
__device__ float g_h[2][H_SZ * B_SZ];                   // hidden, k-major [k][b]
__device__ float g_xT[H_SZ * B_SZ];                     // decoder input, k-major
__device__ float g_xT_all[L_SZ * H_SZ * B_SZ];          // encoder embeds [t][k][b]
__device__ ull   g_part[NBLK_LOG * B_SZ];               // per-block argmax partials

// ---------------- helpers ----------------
static __device__ __forceinline__ ull pk2(float lo, float hi) {
    ull r; asm("mov.b64 %0, {%1, %2};" : "=l"(r) : "f"(lo), "f"(hi)); return r;
}
static __device__ __forceinline__ void ffma2(ull& d, ull a, ull b) {
    asm("fma.rn.f32x2 %0, %1, %2, %0;" : "+l"(d) : "l"(a), "l"(b));
}
static __device__ __forceinline__ float2 upk2(ull v) {
    float2 r; asm("mov.b64 {%0, %1}, %2;" : "=f"(r.x), "=f"(r.y) : "l"(v)); return r;
}
static __device__ __forceinline__ unsigned ordf(float f) {
    unsigned u = __float_as_uint(f);
    return (u & 0x80000000u) ? ~u : (u | 0x80000000u);
}
static __device__ __forceinline__ ull umax64(ull a, ull b) { return a > b ? a : b; }
static __device__ __forceinline__ float sigd(float x) {
    return (float)(1.0 / (1.0 + exp(-(double)x)));
}
static __device__ __forceinline__ float tanhd(float x) { return (float)tanh((double)x); }

// ---------------- setup: zero h0, decoder x0 = relu(emb[0]) ----------------
__global__ void k_init(const float* __restrict__ emb) {
    int i = blockIdx.x * 256 + threadIdx.x;          // 75*256 = 19200 exact
    g_h[0][i] = 0.0f;
    g_xT[i] = fmaxf(emb[i >> 6], 0.0f);              // [k][b], emb row 0
}

// ---------------- gather encoder embeddings: xT_all[t][k][b] ----------------
__global__ void k_gather_enc(const int* __restrict__ input, const float* __restrict__ emb) {
    __shared__ int ids[B_SZ];
    int t = blockIdx.x, tid = threadIdx.x;
    if (tid < B_SZ) ids[tid] = input[t * B_SZ + tid];
    __syncthreads();
    for (int i = tid; i < B_SZ * H_SZ; i += 256) {
        int b = i / H_SZ, k = i - b * H_SZ;
        g_xT_all[((size_t)t * H_SZ + k) * B_SZ + b] = emb[(size_t)ids[b] * H_SZ + k];
    }
}

// ---------------- GRU step: h_new[n][b] from x,h (k-major) ----------------
// grid 75 (4 n per block), block 256: thread (n = tid>>6, b = tid&63)
__global__ __launch_bounds__(256) void k_gru(
    const float* __restrict__ W_ih, const float* __restrict__ W_hh,
    const float* __restrict__ b_ih, const float* __restrict__ b_hh,
    int xoff, int hin, int hout)
{
    __shared__ __align__(16) float Ws[24][304];   // 6 gates x 4 n, k-contig
    int tid = threadIdx.x, blk = blockIdx.x;
    int n = tid >> 6, b = tid & 63;
    int ng = blk * 4 + n;

    for (int i = tid; i < 24 * 75; i += 256) {    // 1800 float4s
        int r = i / 75, q = i - r * 75;
        int g = r >> 2, nn = r & 3;
        const float* src = (g < 3)
            ? W_ih + (size_t)(g * H_SZ + blk * 4 + nn) * H_SZ
            : W_hh + (size_t)((g - 3) * H_SZ + blk * 4 + nn) * H_SZ;
        *(float4*)(&Ws[r][q * 4]) = *(const float4*)(src + q * 4);
    }
    __syncthreads();

    const float* xp = (xoff >= 0) ? (g_xT_all + xoff) : g_xT;
    const float* hp = g_h[hin];
    const float* w0 = Ws[n];      const float* w1 = Ws[4 + n];
    const float* w2 = Ws[8 + n];  const float* w3 = Ws[12 + n];
    const float* w4 = Ws[16 + n]; const float* w5 = Ws[20 + n];

    float a0 = 0, a1 = 0, a2 = 0, a3 = 0, a4 = 0, a5 = 0;
    for (int k = 0; k < H_SZ; k += 4) {
        float4 W0 = *(const float4*)(w0 + k), W1 = *(const float4*)(w1 + k);
        float4 W2 = *(const float4*)(w2 + k), W3 = *(const float4*)(w3 + k);
        float4 W4 = *(const float4*)(w4 + k), W5 = *(const float4*)(w5 + k);
        float x0 = xp[k * 64 + b],  x1 = xp[(k + 1) * 64 + b];
        float x2 = xp[(k + 2) * 64 + b], x3 = xp[(k + 3) * 64 + b];
        float h0 = hp[k * 64 + b],  h1 = hp[(k + 1) * 64 + b];
        float h2 = hp[(k + 2) * 64 + b], h3 = hp[(k + 3) * 64 + b];
        a0 = fmaf(W0.x, x0, a0); a0 = fmaf(W0.y, x1, a0); a0 = fmaf(W0.z, x2, a0); a0 = fmaf(W0.w, x3, a0);
        a1 = fmaf(W1.x, x0, a1); a1 = fmaf(W1.y, x1, a1); a1 = fmaf(W1.z, x2, a1); a1 = fmaf(W1.w, x3, a1);
        a2 = fmaf(W2.x, x0, a2); a2 = fmaf(W2.y, x1, a2); a2 = fmaf(W2.z, x2, a2); a2 = fmaf(W2.w, x3, a2);
        a3 = fmaf(W3.x, h0, a3); a3 = fmaf(W3.y, h1, a3); a3 = fmaf(W3.z, h2, a3); a3 = fmaf(W3.w, h3, a3);
        a4 = fmaf(W4.x, h0, a4); a4 = fmaf(W4.y, h1, a4); a4 = fmaf(W4.z, h2, a4); a4 = fmaf(W4.w, h3, a4);
        a5 = fmaf(W5.x, h0, a5); a5 = fmaf(W5.y, h1, a5); a5 = fmaf(W5.z, h2, a5); a5 = fmaf(W5.w, h3, a5);
    }

    float r = sigd(a0 + b_ih[ng] + a3 + b_hh[ng]);
    float z = sigd(a1 + b_ih[300 + ng] + a4 + b_hh[300 + ng]);
    float nn_ = tanhd(a2 + b_ih[600 + ng] + r * (a5 + b_hh[600 + ng]));
    float hold = hp[ng * 64 + b];
    g_h[hout][ng * 64 + b] = (1.0f - z) * nn_ + z * hold;
}

// ---------------- logits GEMM + fused per-block argmax ----------------
// grid 782, block 256: thread (vy = tid>>3 -> 4 vocab rows, bx = tid&7 -> 8 batches)
__global__ __launch_bounds__(256) void k_logits(
    int hin, const float* __restrict__ W, const float* __restrict__ bias)
{
    __shared__ __align__(16) char sraw[16384];
    float* Wt = (float*)sraw;                 // [128][21] (padded, conflict-free)
    float* hs = (float*)(sraw + 10752);       // [20][64]
    ull*   red = (ull*)sraw;                  // [32][64], reused after compute

    int tid = threadIdx.x, blk = blockIdx.x;
    int v0 = blk * VB;
    int vy = tid >> 3, bx = tid & 7;
    const float* hT = g_h[hin];

    ull acc[4][4];
#pragma unroll
    for (int i = 0; i < 4; i++)
#pragma unroll
        for (int j = 0; j < 4; j++) acc[i][j] = 0ull;

    for (int c = 0; c < H_SZ / KCH; c++) {    // 15 chunks
        int k0 = c * KCH;
        for (int i = tid; i < VB * 5; i += 256) {       // 640 float4 of W
            int vl = i / 5, q = i - vl * 5;
            int rv = v0 + vl; if (rv > V_SZ - 1) rv = V_SZ - 1;
            float4 w = *(const float4*)(W + (size_t)rv * H_SZ + k0 + q * 4);
            float* d = Wt + vl * 21 + q * 4;
            d[0] = w.x; d[1] = w.y; d[2] = w.z; d[3] = w.w;
        }
        for (int i = tid; i < KCH * 16; i += 256) {     // 320 float4 of h
            int kk = i >> 4, q = i & 15;
            *(float4*)(hs + kk * 64 + q * 4) = *(const float4*)(hT + (k0 + kk) * 64 + q * 4);
        }
        __syncthreads();
#pragma unroll
        for (int kk = 0; kk < KCH; kk++) {
            const ull* hq = (const ull*)(hs + kk * 64 + bx * 8);
            ull h0 = hq[0], h1 = hq[1], h2 = hq[2], h3 = hq[3];
            const float* wp = Wt + (vy * 4) * 21 + kk;
            ull w;
            w = pk2(wp[0], wp[0]);
            ffma2(acc[0][0], w, h0); ffma2(acc[0][1], w, h1); ffma2(acc[0][2], w, h2); ffma2(acc[0][3], w, h3);
            w = pk2(wp[21], wp[21]);
            ffma2(acc[1][0], w, h0); ffma2(acc[1][1], w, h1); ffma2(acc[1][2], w, h2); ffma2(acc[1][3], w, h3);
            w = pk2(wp[42], wp[42]);
            ffma2(acc[2][0], w, h0); ffma2(acc[2][1], w, h1); ffma2(acc[2][2], w, h2); ffma2(acc[2][3], w, h3);
            w = pk2(wp[63], wp[63]);
            ffma2(acc[3][0], w, h0); ffma2(acc[3][1], w, h1); ffma2(acc[3][2], w, h2); ffma2(acc[3][3], w, h3);
        }
        __syncthreads();
    }

    // fused argmax: keys (ordered_float<<32) | ~v  (JAX first-index tie-break)
    ull lmax[8];
#pragma unroll
    for (int j = 0; j < 8; j++) lmax[j] = 0ull;
#pragma unroll
    for (int iv = 0; iv < 4; iv++) {
        int v = v0 + vy * 4 + iv;
        bool ok = (v < V_SZ);
        float bj = bias[ok ? v : 0];
#pragma unroll
        for (int cc = 0; cc < 4; cc++) {
            float2 p = upk2(acc[iv][cc]);
            float va = p.x + bj, vb = p.y + bj;
            ull ka = ok ? (((ull)ordf(va) << 32) | (ull)(~(unsigned)v)) : 0ull;
            ull kb = ok ? (((ull)ordf(vb) << 32) | (ull)(~(unsigned)v)) : 0ull;
            lmax[2 * cc]     = umax64(lmax[2 * cc], ka);
            lmax[2 * cc + 1] = umax64(lmax[2 * cc + 1], kb);
        }
    }
#pragma unroll
    for (int j = 0; j < 8; j++) red[vy * 64 + bx * 8 + j] = lmax[j];
    __syncthreads();
    if (tid < B_SZ) {
        ull m = red[tid];
#pragma unroll 4
        for (int r = 1; r < 32; r++) m = umax64(m, red[r * 64 + tid]);
        g_part[blk * B_SZ + tid] = m;
    }
}

// ---------------- finalize: global argmax per batch, emit id, gather next x ----
__global__ void k_finalize(const float* __restrict__ emb, float* __restrict__ out, int t) {
    __shared__ ull sred[256];
    __shared__ int sid;
    int b = blockIdx.x, tid = threadIdx.x;
    ull m = 0;
    for (int i = tid; i < NBLK_LOG; i += 256) m = umax64(m, g_part[i * B_SZ + b]);
    sred[tid] = m;
    __syncthreads();
    for (int s = 128; s > 0; s >>= 1) {
        if (tid < s) sred[tid] = umax64(sred[tid], sred[tid + s]);
        __syncthreads();
    }
    if (tid == 0) {
        unsigned id = ~(unsigned)(sred[0] & 0xffffffffull);
        sid = (int)id;
        out[t * B_SZ + b] = (float)id;
    }
    __syncthreads();
    int id = sid;
    for (int k = tid; k < H_SZ; k += 256)
        g_xT[k * 64 + b] = fmaxf(emb[(size_t)id * H_SZ + k], 0.0f);
}

// ---------------- launch ----------------
extern "C" void kernel_launch(void* const* d_in, const int* in_sizes, int n_in,
                              void* d_out, int out_size) {
    const int*   input = (const int*)d_in[0];
    const float* emb   = (const float*)d_in[1];
    const float* eWih  = (const float*)d_in[2];
    const float* eWhh  = (const float*)d_in[3];
    const float* ebih  = (const float*)d_in[4];
    const float* ebhh  = (const float*)d_in[5];
    const float* dWih  = (const float*)d_in[6];
    const float* dWhh  = (const float*)d_in[7];
    const float* dbih  = (const float*)d_in[8];
    const float* dbhh  = (const float*)d_in[9];
    const float* oW    = (const float*)d_in[10];
    const float* ob    = (const float*)d_in[11];
    float* out = (float*)d_out;

    k_init<<<75, 256>>>(emb);
    k_gather_enc<<<L_SZ, 256>>>(input, emb);

    // encoder: 64 GRU steps, ping-pong h
    for (int t = 0; t < L_SZ; t++)
        k_gru<<<75, 256>>>(eWih, eWhh, ebih, ebhh, t * H_SZ * B_SZ, t & 1, (t + 1) & 1);

    // decoder: h starts in g_h[0]
    int p = 0;
    for (int t = 0; t < L_SZ; t++) {
        k_gru<<<75, 256>>>(dWih, dWhh, dbih, dbhh, -1, p, 1 - p);
        k_logits<<<NBLK_LOG, 256>>>(1 - p, oW, ob);
        k_finalize<<<B_SZ, 256>>>(emb, out, t);
        p = 1 - p;
    }
}

// round 3
// speedup vs baseline: 1.6794x; 1.6794x over previous
#include <cuda_runtime.h>
#include <cstdint>
#include <math.h>

#define V_SZ 100000
#define H_SZ 300
#define HP   304          // padded K (pads are zero-weighted)
#define B_SZ 64
#define L_SZ 64
#define KCH  20
#define VB   128
#define NBLK_LOG 782      // 782*128 = 100096 >= V_SZ

typedef unsigned long long ull;

// ---------------- device scratch (no allocations allowed) ----------------
__device__ __align__(16) float g_h[2][HP * B_SZ];           // hidden, [k][b]
__device__ __align__(16) float g_xT[HP * B_SZ];             // decoder input
__device__ __align__(16) float g_xT_all[L_SZ * HP * B_SZ];  // encoder embeds
__device__ ull g_part[NBLK_LOG * B_SZ];

// ---------------- helpers ----------------
static __device__ __forceinline__ ull pk2(float lo, float hi) {
    ull r; asm("mov.b64 %0, {%1, %2};" : "=l"(r) : "f"(lo), "f"(hi)); return r;
}
static __device__ __forceinline__ void ffma2(ull& d, ull a, ull b) {
    asm("fma.rn.f32x2 %0, %1, %2, %0;" : "+l"(d) : "l"(a), "l"(b));
}
static __device__ __forceinline__ float2 upk2(ull v) {
    float2 r; asm("mov.b64 {%0, %1}, %2;" : "=f"(r.x), "=f"(r.y) : "l"(v)); return r;
}
static __device__ __forceinline__ unsigned ordf(float f) {
    unsigned u = __float_as_uint(f);
    return (u & 0x80000000u) ? ~u : (u | 0x80000000u);
}
static __device__ __forceinline__ ull umax64(ull a, ull b) { return a > b ? a : b; }
static __device__ __forceinline__ float sigd(float x) {
    return (float)(1.0 / (1.0 + exp(-(double)x)));
}
static __device__ __forceinline__ float tanhd(float x) { return (float)tanh((double)x); }
static __device__ __forceinline__ unsigned s2u(const void* p) {
    return (unsigned)__cvta_generic_to_shared(p);
}
#define CP16(dst, src) asm volatile("cp.async.cg.shared.global [%0], [%1], 16;" :: "r"(dst), "l"(src))

// ---------------- init: zero h0 (incl pads), decoder x0 = relu(emb[0]) ----
__global__ void k_init(const float* __restrict__ emb) {
    int i = blockIdx.x * 256 + threadIdx.x;    // 76*256 = 19456 = HP*64 exact
    int k = i >> 6;
    g_h[0][i] = 0.0f;
    g_xT[i] = (k < H_SZ) ? fmaxf(emb[k], 0.0f) : 0.0f;
}

// ---------------- gather encoder embeddings ----------------
__global__ void k_gather_enc(const int* __restrict__ input, const float* __restrict__ emb) {
    __shared__ int ids[B_SZ];
    int t = blockIdx.x, tid = threadIdx.x;
    if (tid < B_SZ) ids[tid] = input[t * B_SZ + tid];
    __syncthreads();
    for (int i = tid; i < B_SZ * H_SZ; i += 256) {
        int b = i / H_SZ, k = i - b * H_SZ;
        g_xT_all[((size_t)t * HP + k) * B_SZ + b] = emb[(size_t)ids[b] * H_SZ + k];
    }
}

// ---------------- GRU step: grid 100 (3 n/block), block 256 --------------
// thread = (s = tid>>4 : 16 K-slices of 19, bq = tid&15 : 4 batches)
__global__ __launch_bounds__(256) void k_gru(
    const float* __restrict__ W_ih, const float* __restrict__ W_hh,
    const float* __restrict__ b_ih, const float* __restrict__ b_hh,
    int xoff, int hin, int hout)
{
    __shared__ __align__(16) char smraw[36864];
    float (*Ws)[HP] = (float(*)[HP])smraw;    // [18][304] during main loop
    float* Red = (float*)smraw;               // [8][18][64] after (union)

    int tid = threadIdx.x;
    int n0 = blockIdx.x * 3;

    // stage 18 weight rows (rows 0..8: W_ih g*3+nl; 9..17: W_hh)
    for (int i = tid; i < 18 * 75; i += 256) {
        int row = i / 75, q = i - row * 75;
        int rr = (row < 9) ? row : row - 9;
        int g = rr / 3, nl = rr - g * 3;
        const float* src = ((row < 9) ? W_ih : W_hh) + (size_t)(g * H_SZ + n0 + nl) * H_SZ;
        *(float4*)&Ws[row][q * 4] = *(const float4*)(src + q * 4);
    }
    if (tid < 18) { float4 z = {0.f, 0.f, 0.f, 0.f}; *(float4*)&Ws[tid][300] = z; }
    __syncthreads();

    const float* xp = (xoff >= 0) ? (g_xT_all + xoff) : g_xT;
    const float* hp = g_h[hin];
    int s = tid >> 4, bq = tid & 15;
    int ks = s * 19;

    ull a[18][2];
#pragma unroll
    for (int r = 0; r < 18; r++) { a[r][0] = 0ull; a[r][1] = 0ull; }

#pragma unroll 4
    for (int k = ks; k < ks + 19; k++) {
        ulonglong2 xq = *(const ulonglong2*)(xp + k * 64 + bq * 4);
        ulonglong2 hq = *(const ulonglong2*)(hp + k * 64 + bq * 4);
#pragma unroll
        for (int r = 0; r < 9; r++) {
            float wv = Ws[r][k];
            ull wd = pk2(wv, wv);
            ffma2(a[r][0], wd, xq.x);
            ffma2(a[r][1], wd, xq.y);
        }
#pragma unroll
        for (int r = 9; r < 18; r++) {
            float wv = Ws[r][k];
            ull wd = pk2(wv, wv);
            ffma2(a[r][0], wd, hq.x);
            ffma2(a[r][1], wd, hq.y);
        }
    }
    __syncthreads();   // done reading Ws (smem union with Red)

    // combine slice pairs (s, s^1) via shuffle, even-s lanes write partials
#pragma unroll
    for (int r = 0; r < 18; r++) {
        ull o0 = __shfl_xor_sync(0xffffffffu, a[r][0], 16);
        ull o1 = __shfl_xor_sync(0xffffffffu, a[r][1], 16);
        if ((tid & 16) == 0) {
            float2 p0 = upk2(a[r][0]), p1 = upk2(a[r][1]);
            float2 q0 = upk2(o0), q1 = upk2(o1);
            float4 v;
            v.x = p0.x + q0.x; v.y = p0.y + q0.y;
            v.z = p1.x + q1.x; v.w = p1.y + q1.y;
            *(float4*)&Red[(s >> 1) * 1152 + r * 64 + bq * 4] = v;
        }
    }
    __syncthreads();

    if (tid < 192) {
        int nl = tid >> 6, b = tid & 63;
        float sir = 0, siz = 0, sin_ = 0, shr = 0, shz = 0, shn = 0;
#pragma unroll
        for (int s2 = 0; s2 < 8; s2++) {
            const float* base = Red + s2 * 1152;
            sir  += base[nl * 64 + b];
            siz  += base[(3 + nl) * 64 + b];
            sin_ += base[(6 + nl) * 64 + b];
            shr  += base[(9 + nl) * 64 + b];
            shz  += base[(12 + nl) * 64 + b];
            shn  += base[(15 + nl) * 64 + b];
        }
        int n = n0 + nl;
        float r = sigd(sir + b_ih[n] + shr + b_hh[n]);
        float z = sigd(siz + b_ih[H_SZ + n] + shz + b_hh[H_SZ + n]);
        float nn = tanhd(sin_ + b_ih[2 * H_SZ + n] + r * (shn + b_hh[2 * H_SZ + n]));
        float hold = hp[n * 64 + b];
        g_h[hout][n * 64 + b] = (1.0f - z) * nn + z * hold;
    }
}

// ---------------- logits GEMM + fused per-block argmax -------------------
// grid 782, block 256 = (vy = tid>>4 : 8 vocab rows, bx = tid&15 : 4 batches)
__global__ __launch_bounds__(256) void k_logits(
    int hin, const float* __restrict__ W, const float* __restrict__ bias)
{
    __shared__ __align__(16) char sm[17664];
    float* Wt = (float*)sm;               // 128 rows x 24 floats, +16B skew /8 rows
    float* hs = (float*)(sm + 12544);     // [20][64]

    int tid = threadIdx.x, blk = blockIdx.x;
    int v0 = blk * VB;
    int vy = tid >> 4, bx = tid & 15;
    const float* hT = g_h[hin];

    ull acc[8][2];
#pragma unroll
    for (int i = 0; i < 8; i++) { acc[i][0] = 0ull; acc[i][1] = 0ull; }

    for (int c = 0; c < H_SZ / KCH; c++) {    // 15 chunks
        int k0 = c * KCH;
        // stage W chunk: 640 x 16B via cp.async (skewed dst: conflict-free LDS.128)
        for (int i = tid; i < VB * 5; i += 256) {
            int vl = i / 5, q = i - vl * 5;
            int rv = v0 + vl; if (rv > V_SZ - 1) rv = V_SZ - 1;
            unsigned dst = s2u(Wt + vl * 24 + (vl >> 3) * 4 + q * 4);
            CP16(dst, W + (size_t)rv * H_SZ + k0 + q * 4);
        }
        // stage h chunk: 320 x 16B (contiguous)
        const float* hb = hT + k0 * 64;
        for (int i = tid; i < 320; i += 256) {
            CP16(s2u(hs + i * 4), hb + i * 4);
        }
        asm volatile("cp.async.commit_group;");
        asm volatile("cp.async.wait_group 0;");
        __syncthreads();

        const float* wrow = Wt + vy * 196;    // row base: vy*784 bytes
#pragma unroll
        for (int kk = 0; kk < KCH; kk += 4) {
            ulonglong2 h0 = *(const ulonglong2*)(hs + (kk + 0) * 64 + bx * 4);
            ulonglong2 h1 = *(const ulonglong2*)(hs + (kk + 1) * 64 + bx * 4);
            ulonglong2 h2 = *(const ulonglong2*)(hs + (kk + 2) * 64 + bx * 4);
            ulonglong2 h3 = *(const ulonglong2*)(hs + (kk + 3) * 64 + bx * 4);
#pragma unroll
            for (int iv = 0; iv < 8; iv++) {
                float4 wv = *(const float4*)(wrow + iv * 24 + kk);
                ull w0 = pk2(wv.x, wv.x), w1 = pk2(wv.y, wv.y);
                ull w2 = pk2(wv.z, wv.z), w3 = pk2(wv.w, wv.w);
                ffma2(acc[iv][0], w0, h0.x); ffma2(acc[iv][1], w0, h0.y);
                ffma2(acc[iv][0], w1, h1.x); ffma2(acc[iv][1], w1, h1.y);
                ffma2(acc[iv][0], w2, h2.x); ffma2(acc[iv][1], w2, h2.y);
                ffma2(acc[iv][0], w3, h3.x); ffma2(acc[iv][1], w3, h3.y);
            }
        }
        __syncthreads();   // protect Wt/hs before next chunk's cp.async
    }

    // fused argmax: key = (ordered_float << 32) | ~v  (JAX first-index ties)
    float bj[8];
    if (v0 + VB <= V_SZ) {
        float4 b0 = *(const float4*)(bias + v0 + vy * 8);
        float4 b1 = *(const float4*)(bias + v0 + vy * 8 + 4);
        bj[0] = b0.x; bj[1] = b0.y; bj[2] = b0.z; bj[3] = b0.w;
        bj[4] = b1.x; bj[5] = b1.y; bj[6] = b1.z; bj[7] = b1.w;
    } else {
#pragma unroll
        for (int iv = 0; iv < 8; iv++) {
            int v = v0 + vy * 8 + iv;
            bj[iv] = bias[v < V_SZ ? v : V_SZ - 1];
        }
    }
    ull lm[4] = {0ull, 0ull, 0ull, 0ull};
#pragma unroll
    for (int iv = 0; iv < 8; iv++) {
        int v = v0 + vy * 8 + iv;
        if (v < V_SZ) {
            float2 p0 = upk2(acc[iv][0]), p1 = upk2(acc[iv][1]);
            ull t = (ull)(~(unsigned)v);
            lm[0] = umax64(lm[0], ((ull)ordf(p0.x + bj[iv]) << 32) | t);
            lm[1] = umax64(lm[1], ((ull)ordf(p0.y + bj[iv]) << 32) | t);
            lm[2] = umax64(lm[2], ((ull)ordf(p1.x + bj[iv]) << 32) | t);
            lm[3] = umax64(lm[3], ((ull)ordf(p1.y + bj[iv]) << 32) | t);
        }
    }
    ull* red = (ull*)sm;                  // 16 vy x 64 b (8KB, reuse smem)
#pragma unroll
    for (int j = 0; j < 4; j++) red[vy * 64 + bx * 4 + j] = lm[j];
    __syncthreads();
    if (tid < B_SZ) {
        ull m = red[tid];
#pragma unroll
        for (int r = 1; r < 16; r++) m = umax64(m, red[r * 64 + tid]);
        g_part[blk * B_SZ + tid] = m;
    }
}

// ---------------- finalize: global argmax per batch, emit id, next x -----
__global__ void k_finalize(const float* __restrict__ emb, float* __restrict__ out, int t) {
    __shared__ ull sred[256];
    __shared__ int sid;
    int b = blockIdx.x, tid = threadIdx.x;
    ull m = 0;
    for (int i = tid; i < NBLK_LOG; i += 256) m = umax64(m, g_part[i * B_SZ + b]);
    sred[tid] = m;
    __syncthreads();
    for (int s = 128; s > 0; s >>= 1) {
        if (tid < s) sred[tid] = umax64(sred[tid], sred[tid + s]);
        __syncthreads();
    }
    if (tid == 0) {
        unsigned id = ~(unsigned)(sred[0] & 0xffffffffull);
        sid = (int)id;
        out[t * B_SZ + b] = (float)id;
    }
    __syncthreads();
    int id = sid;
    for (int k = tid; k < H_SZ; k += 256)
        g_xT[k * 64 + b] = fmaxf(emb[(size_t)id * H_SZ + k], 0.0f);
}

// ---------------- launch ----------------
extern "C" void kernel_launch(void* const* d_in, const int* in_sizes, int n_in,
                              void* d_out, int out_size) {
    const int*   input = (const int*)d_in[0];
    const float* emb   = (const float*)d_in[1];
    const float* eWih  = (const float*)d_in[2];
    const float* eWhh  = (const float*)d_in[3];
    const float* ebih  = (const float*)d_in[4];
    const float* ebhh  = (const float*)d_in[5];
    const float* dWih  = (const float*)d_in[6];
    const float* dWhh  = (const float*)d_in[7];
    const float* dbih  = (const float*)d_in[8];
    const float* dbhh  = (const float*)d_in[9];
    const float* oW    = (const float*)d_in[10];
    const float* ob    = (const float*)d_in[11];
    float* out = (float*)d_out;

    k_init<<<76, 256>>>(emb);
    k_gather_enc<<<L_SZ, 256>>>(input, emb);

    // encoder: 64 GRU steps, ping-pong h (ends in g_h[0])
    for (int t = 0; t < L_SZ; t++)
        k_gru<<<100, 256>>>(eWih, eWhh, ebih, ebhh, t * HP * B_SZ, t & 1, (t + 1) & 1);

    // decoder
    int p = 0;
    for (int t = 0; t < L_SZ; t++) {
        k_gru<<<100, 256>>>(dWih, dWhh, dbih, dbhh, -1, p, 1 - p);
        k_logits<<<NBLK_LOG, 256>>>(1 - p, oW, ob);
        k_finalize<<<B_SZ, 256>>>(emb, out, t);
        p = 1 - p;
    }
}